// round 6
// baseline (speedup 1.0000x reference)
#include <cuda_runtime.h>
#include <math.h>

#define HW    80
#define NPIX  6400          // 80*80
#define NPAIR 32            // B*L*L
#define NIMG  8             // B*L

typedef unsigned long long ull;

// ---------------- scratch (static __device__, no allocations) ----------------
__device__ float g_minv[NPAIR * 6];
__device__ float g_mask[NPAIR * NPIX];
__device__ float g_masksum[NIMG * NPIX];
__device__ float g_y[NIMG * 64 * NPIX];        // y (iter input) / h1
__device__ float g_nbr[NPAIR * 64 * NPIX];     // warped neighbors
__device__ float g_convn[NPAIR * 64 * NPIX];   // conv(neighbor)
__device__ float g_ego[NIMG * 64 * NPIX];      // conv(ego)+bias
__device__ float g_agg[NIMG * 64 * NPIX];      // masked mean
__device__ float g_gru[NIMG * 128 * NPIX];     // [update|cand] logits
__device__ float g_unbr[16 * 64 * 64];         // Winograd U: [tap][ci][co]
__device__ float g_uego[16 * 64 * 64];
__device__ float g_ugru[16 * 128 * 128];
__device__ float g_bgru[128];

// ---------------- packed fp32x2 helpers (sm_103a FFMA2) ----------------
__device__ __forceinline__ void fma2(ull& d, ull a, ull b) {
    asm("fma.rn.f32x2 %0, %1, %2, %0;" : "+l"(d) : "l"(a), "l"(b));
}
__device__ __forceinline__ ull bcast2(float v) {
    ull r;
    asm("mov.b64 %0, {%1, %1};" : "=l"(r) : "f"(v));
    return r;
}

// accurate activations (avoid fast-math tanh.approx)
__device__ __forceinline__ float sigmoid_acc(float u) {
    return 1.0f / (1.0f + expf(-u));
}
__device__ __forceinline__ float tanh_acc(float x) {
    float a = fabsf(x);
    float e = expf(-2.0f * a);
    float t = (1.0f - e) / (1.0f + e);
    return copysignf(t, x);
}

// ---------------- affine inverse: replicate reference fp32 arithmetic -------
__global__ void k_minv(const float* __restrict__ P) {
    int p = threadIdx.x;
    if (p >= NPAIR) return;
    const float* M = P + p * 16;
    float a = M[0], b = M[1];
    float c = M[4], d = M[5];
    float txs = __fdiv_rn(M[3], 0.8f);
    float tys = __fdiv_rn(M[7], 0.8f);
    const float cx = 40.0f, cy = 40.0f;
    float dot0 = __fadd_rn(__fmul_rn(a, cx), __fmul_rn(b, cy));
    float dot1 = __fadd_rn(__fmul_rn(c, cx), __fmul_rn(d, cy));
    float Tx = __fadd_rn(__fsub_rn(cx, dot0), txs);
    float Ty = __fadd_rn(__fsub_rn(cy, dot1), tys);

    float ra  = __fdiv_rn(1.0f, a);
    float l10 = __fmul_rn(c, ra);
    float u22 = __fmaf_rn(-l10, b, d);
    float u23 = __fmaf_rn(-l10, Tx, Ty);

    float x1_0 = __fdiv_rn(-l10, u22);
    float x0_0 = __fdiv_rn(__fmaf_rn(-b, x1_0, 1.0f), a);
    float x1_1 = __fdiv_rn(1.0f, u22);
    float x0_1 = __fdiv_rn(__fmul_rn(-b, x1_1), a);
    float x1_2 = __fdiv_rn(-u23, u22);
    float x0_2 = __fdiv_rn(__fmaf_rn(-b, x1_2, -Tx), a);

    float* o = g_minv + p * 6;
    o[0] = x0_0; o[1] = x0_1; o[2] = x0_2;
    o[3] = x1_0; o[4] = x1_1; o[5] = x1_2;
}

__device__ __forceinline__ float coordx(const float* mv, float x, float y) {
    float s = __fmul_rn(mv[0], x);
    s = __fmaf_rn(mv[1], y, s);
    return __fadd_rn(s, mv[2]);
}
__device__ __forceinline__ float coordy(const float* mv, float x, float y) {
    float s = __fmul_rn(mv[3], x);
    s = __fmaf_rn(mv[4], y, s);
    return __fadd_rn(s, mv[5]);
}

// ---------------- nearest-warp validity mask ----------------
__global__ void k_mask() {
    int pair = blockIdx.y;
    int p = blockIdx.x * 256 + threadIdx.x;
    if (p >= NPIX) return;
    const float* mv = g_minv + pair * 6;
    float x = (float)(p % HW), y = (float)(p / HW);
    float sx = coordx(mv, x, y);
    float sy = coordy(mv, x, y);
    int ix = (int)rintf(sx);
    int iy = (int)rintf(sy);
    g_mask[pair * NPIX + p] =
        (ix >= 0 && ix < HW && iy >= 0 && iy < HW) ? 1.0f : 0.0f;
}

__global__ void k_masksum() {
    int bj = blockIdx.y;
    int p = blockIdx.x * 256 + threadIdx.x;
    if (p >= NPIX) return;
    int b = bj >> 2, j = bj & 3;
    float s = 0.0f;
#pragma unroll
    for (int i = 0; i < 4; i++)
        s += g_mask[((b * 4 + i) * 4 + j) * NPIX + p];
    g_masksum[bj * NPIX + p] = s;
}

// ---------------- initial transform: y[c,h,w] = x[c, 79-w, h] ----------------
__global__ void k_transform(const float* __restrict__ x) {
    int idx = blockIdx.x * 256 + threadIdx.x;
    int p = idx % NPIX;
    int c = (idx / NPIX) & 63;
    int bl = idx / (NPIX * 64);
    int h = p / HW, w = p % HW;
    g_y[idx] = x[(bl * 64 + c) * NPIX + (HW - 1 - w) * HW + h];
}

// ---------------- bilinear warp of y[b,i] by T[pair] ----------------
__global__ void k_warp() {
    int pair = blockIdx.y;
    int p = blockIdx.x * 256 + threadIdx.x;
    if (p >= NPIX) return;
    int b = pair >> 4;
    int i = (pair >> 2) & 3;
    const float* mv = g_minv + pair * 6;
    float x = (float)(p % HW), y = (float)(p / HW);
    float sx = coordx(mv, x, y);
    float sy = coordy(mv, x, y);
    float x0f = floorf(sx), y0f = floorf(sy);
    float fx = __fsub_rn(sx, x0f), fy = __fsub_rn(sy, y0f);
    int x0 = (int)x0f, y0 = (int)y0f;
    int x1 = x0 + 1, y1 = y0 + 1;
    int cx0 = min(max(x0, 0), HW - 1), cx1 = min(max(x1, 0), HW - 1);
    int cy0 = min(max(y0, 0), HW - 1), cy1 = min(max(y1, 0), HW - 1);
    float vx0 = (x0 >= 0 && x0 < HW) ? 1.0f : 0.0f;
    float vx1 = (x1 >= 0 && x1 < HW) ? 1.0f : 0.0f;
    float vy0 = (y0 >= 0 && y0 < HW) ? 1.0f : 0.0f;
    float vy1 = (y1 >= 0 && y1 < HW) ? 1.0f : 0.0f;
    float gx = __fsub_rn(1.0f, fx), gy = __fsub_rn(1.0f, fy);
    float w00 = __fmul_rn(__fmul_rn(vx0, vy0), __fmul_rn(gx, gy));
    float w10 = __fmul_rn(__fmul_rn(vx1, vy0), __fmul_rn(fx, gy));
    float w01 = __fmul_rn(__fmul_rn(vx0, vy1), __fmul_rn(gx, fy));
    float w11 = __fmul_rn(__fmul_rn(vx1, vy1), __fmul_rn(fx, fy));
    int i00 = cy0 * HW + cx0, i10 = cy0 * HW + cx1;
    int i01 = cy1 * HW + cx0, i11 = cy1 * HW + cx1;
    const float* src = g_y + (b * 4 + i) * 64 * NPIX;
    float* dst = g_nbr + pair * 64 * NPIX;
#pragma unroll 4
    for (int c = 0; c < 64; c++) {
        const float* sc = src + c * NPIX;
        float v = __fmul_rn(w00, sc[i00]);
        v = __fadd_rn(v, __fmul_rn(w10, sc[i10]));
        v = __fadd_rn(v, __fmul_rn(w01, sc[i01]));
        v = __fadd_rn(v, __fmul_rn(w11, sc[i11]));
        dst[c * NPIX + p] = v;
    }
}

// ============== Winograd F(2x2,3x3) fused conv =================
// Block: 256 thr, 16x8 px output region (32 tiles of 2x2), 32 couts.
// Phases per 8-ci slice: stage raw -> B^T d B transform -> 16-tap GEMM
// (f32x2 over tile pairs) -> (after all slices) A^T M A epilogue.
// smem union: [raw 1440 | V 16*258 | U 16*260] vs [M 16*32*34]
#define SM_RAW 0
#define SM_V   1440
#define SM_U   (1440 + 16 * 258)
#define SM_FLOATS (16 * 32 * 34)            // 17408 floats = 69632 B

template <int CIN, int COUT>
__global__ __launch_bounds__(256, 2)
void winog_k(const float* __restrict__ inA, int inA_stride,
             const float* __restrict__ inB, int inB_stride, int splitC,
             const float* __restrict__ U,    // [tap][CIN][COUT]
             const float* __restrict__ bias, // may be null
             const float* __restrict__ maskp,// per-img mask or null
             float* __restrict__ outp, int out_stride) {
    extern __shared__ float sm[];
    const int img = blockIdx.z;
    const int couty = blockIdx.y;        // 32-cout slab
    const int cx = blockIdx.x % 5, cy = blockIdx.x / 5;
    const int w0 = cx * 16, h0 = cy * 8;
    const int t = threadIdx.x;

    if (maskp != nullptr) {              // tile skip if fully masked
        const float* mp = maskp + (long)img * NPIX;
        int any = 0;
        if (t < 128)
            any = (mp[(h0 + (t >> 4)) * HW + (w0 + (t & 15))] != 0.0f);
        if (__syncthreads_count(any) == 0) return;
    }

    const int tap = t >> 4, cq = t & 15;

    ull acc0[16], acc1[16];
#pragma unroll
    for (int p = 0; p < 16; p++) { acc0[p] = 0ULL; acc1[p] = 0ULL; }

    for (int cin0 = 0; cin0 < CIN; cin0 += 8) {
        const float* src;
        int cbase;
        if (cin0 < splitC) { src = inA + (long)img * inA_stride; cbase = cin0; }
        else               { src = inB + (long)img * inB_stride; cbase = cin0 - splitC; }
        // ---- stage raw: 8ci x 10 x 18 (with SAME-pad zeros) ----
        for (int idx = t; idx < 1440; idx += 256) {
            int ci = idx / 180, rem = idx % 180;
            int r = rem / 18, c = rem % 18;
            int gh = h0 - 1 + r, gw = w0 - 1 + c;
            float v = 0.0f;
            if (gh >= 0 && gh < HW && gw >= 0 && gw < HW)
                v = src[(cbase + ci) * NPIX + gh * HW + gw];
            sm[SM_RAW + ci * 180 + r * 18 + c] = v;
        }
        // ---- stage U slice: [16 tap][8 ci][32 co] via float4 ----
#pragma unroll
        for (int k = 0; k < 4; k++) {
            int flat = t + k * 256;          // 1024 float4s
            int tp = flat >> 6, rem = flat & 63;
            int ci = rem >> 3, q = rem & 7;
            float4 f = ((const float4*)U)[
                ((long)(tp * CIN + cin0 + ci) * COUT + couty * 32) / 4 + q];
            float4* dstp = (float4*)&sm[SM_U + tp * 260 + ci * 32 + q * 4];
            *dstp = f;
        }
        __syncthreads();
        // ---- input transform: thread = (ci = t>>5, tile = t&31) ----
        {
            int ci = t >> 5, tile = t & 31;
            int th = tile >> 3, tw = tile & 7;
            const float2* base = (const float2*)&sm[SM_RAW + ci * 180];
            float d[4][4];
#pragma unroll
            for (int r = 0; r < 4; r++) {
                float2 a2 = base[(2 * th + r) * 9 + tw];
                float2 b2 = base[(2 * th + r) * 9 + tw + 1];
                d[r][0] = a2.x; d[r][1] = a2.y; d[r][2] = b2.x; d[r][3] = b2.y;
            }
            float tt[4][4];
#pragma unroll
            for (int c = 0; c < 4; c++) {
                tt[0][c] = d[0][c] - d[2][c];
                tt[1][c] = d[1][c] + d[2][c];
                tt[2][c] = d[2][c] - d[1][c];
                tt[3][c] = d[1][c] - d[3][c];
            }
#pragma unroll
            for (int r = 0; r < 4; r++) {
                float v0 = tt[r][0] - tt[r][2];
                float v1 = tt[r][1] + tt[r][2];
                float v2 = tt[r][2] - tt[r][1];
                float v3 = tt[r][1] - tt[r][3];
                sm[SM_V + (r * 4 + 0) * 258 + ci * 32 + tile] = v0;
                sm[SM_V + (r * 4 + 1) * 258 + ci * 32 + tile] = v1;
                sm[SM_V + (r * 4 + 2) * 258 + ci * 32 + tile] = v2;
                sm[SM_V + (r * 4 + 3) * 258 + ci * 32 + tile] = v3;
            }
        }
        __syncthreads();
        // ---- GEMM: M[tap][co][tile] += U[tap][ci][co] * V[tap][ci][tile] ----
#pragma unroll 1
        for (int ci = 0; ci < 8; ci++) {
            ull u0 = bcast2(sm[SM_U + tap * 260 + ci * 32 + 2 * cq]);
            ull u1 = bcast2(sm[SM_U + tap * 260 + ci * 32 + 2 * cq + 1]);
            const ull* vp = (const ull*)&sm[SM_V + tap * 258 + ci * 32];
#pragma unroll
            for (int p = 0; p < 16; p++) {
                ull vt = vp[p];
                fma2(acc0[p], vt, u0);
                fma2(acc1[p], vt, u1);
            }
        }
        __syncthreads();
    }
    // ---- write M to smem (tile-pairs unpack naturally via ull store) ----
#pragma unroll
    for (int p = 0; p < 16; p++) {
        *(ull*)&sm[tap * 1088 + (2 * cq) * 34 + 2 * p] = acc0[p];
        *(ull*)&sm[tap * 1088 + (2 * cq + 1) * 34 + 2 * p] = acc1[p];
    }
    __syncthreads();
    // ---- output transform A^T M A + bias, write 2x2 px ----
#pragma unroll
    for (int k = 0; k < 4; k++) {
        int item = t + k * 256;              // 1024 = 32co x 32tiles
        int co_l = item >> 5, tile = item & 31;
        int th = tile >> 3, tw = tile & 7;
        float m[16];
#pragma unroll
        for (int tp = 0; tp < 16; tp++)
            m[tp] = sm[tp * 1088 + co_l * 34 + tile];
        float t0[4], t1[4];
#pragma unroll
        for (int c = 0; c < 4; c++) {
            t0[c] = m[c] + m[4 + c] + m[8 + c];
            t1[c] = m[4 + c] - m[8 + c] - m[12 + c];
        }
        float y00 = t0[0] + t0[1] + t0[2];
        float y01 = t0[1] - t0[2] - t0[3];
        float y10 = t1[0] + t1[1] + t1[2];
        float y11 = t1[1] - t1[2] - t1[3];
        int co = couty * 32 + co_l;
        float bv = bias ? bias[co] : 0.0f;
        int h = h0 + th * 2, w = w0 + tw * 2;
        float* ob = outp + (long)img * out_stride + co * NPIX;
        ob[h * HW + w]           = y00 + bv;
        ob[h * HW + w + 1]       = y01 + bv;
        ob[(h + 1) * HW + w]     = y10 + bv;
        ob[(h + 1) * HW + w + 1] = y11 + bv;
    }
}

// ---------------- masked mean over i ----------------
__global__ void k_agg() {
    int bj = blockIdx.y;
    int p = blockIdx.x * 256 + threadIdx.x;
    if (p >= NPIX) return;
    int b = bj >> 2, j = bj & 3;
    float ms = g_masksum[bj * NPIX + p];
    float m[4];
#pragma unroll
    for (int i = 0; i < 4; i++)
        m[i] = g_mask[((b * 4 + i) * 4 + j) * NPIX + p];
#pragma unroll 4
    for (int c = 0; c < 64; c++) {
        float v = ms * g_ego[bj * 64 * NPIX + c * NPIX + p];
#pragma unroll
        for (int i = 0; i < 4; i++)
            v += m[i] * g_convn[((b * 4 + i) * 4 + j) * 64 * NPIX + c * NPIX + p];
        g_agg[bj * 64 * NPIX + c * NPIX + p] = 0.25f * v;
    }
}

// ---------------- GRU pointwise: y <- sigmoid(u)*tanh(c) ----------------
__global__ void k_pointwise() {
    int idx = blockIdx.x * 256 + threadIdx.x;
    int p = idx % NPIX;
    int c = (idx / NPIX) & 63;
    int bl = idx / (NPIX * 64);
    float u  = g_gru[bl * 128 * NPIX + c * NPIX + p];
    float cd = g_gru[bl * 128 * NPIX + (64 + c) * NPIX + p];
    g_y[idx] = sigmoid_acc(u) * tanh_acc(cd);
}

// ---------------- Winograd weight transform U = G g G^T ----------------
__device__ __forceinline__ void wino_u(const float* g9, float* U16) {
    float a[4][3];
#pragma unroll
    for (int c = 0; c < 3; c++) {
        float g0 = g9[c], g1 = g9[3 + c], g2 = g9[6 + c];
        a[0][c] = g0;
        a[1][c] = 0.5f * (g0 + g1 + g2);
        a[2][c] = 0.5f * (g0 - g1 + g2);
        a[3][c] = g2;
    }
#pragma unroll
    for (int r = 0; r < 4; r++) {
        U16[r * 4 + 0] = a[r][0];
        U16[r * 4 + 1] = 0.5f * (a[r][0] + a[r][1] + a[r][2]);
        U16[r * 4 + 2] = 0.5f * (a[r][0] - a[r][1] + a[r][2]);
        U16[r * 4 + 3] = a[r][2];
    }
}

__global__ void k_uprep(const float* __restrict__ msg_w,
                        const float* __restrict__ gates_w,
                        const float* __restrict__ gates_b,
                        const float* __restrict__ can_w,
                        const float* __restrict__ can_b) {
    int idx = blockIdx.x * 256 + threadIdx.x;
    float U16[16];
    if (idx < 4096) {                       // neighbor: cin 0..63 of msg_w
        int ci = idx & 63, co = idx >> 6;
        wino_u(msg_w + co * 1152 + ci * 9, U16);
#pragma unroll
        for (int tp = 0; tp < 16; tp++)
            g_unbr[tp * 4096 + ci * 64 + co] = U16[tp];
        return;
    }
    if (idx < 8192) {                       // ego: cin 64..127 of msg_w
        int j = idx - 4096;
        int ci = j & 63, co = j >> 6;
        wino_u(msg_w + co * 1152 + 576 + ci * 9, U16);
#pragma unroll
        for (int tp = 0; tp < 16; tp++)
            g_uego[tp * 4096 + ci * 64 + co] = U16[tp];
        return;
    }
    if (idx < 24576) {                      // gru stacked [update|cand]
        int j = idx - 8192;
        int ci = j & 127, co = j >> 7;
        const float* g9 = (co < 64) ? gates_w + (64 + co) * 1728 + ci * 9
                                    : can_w + (co - 64) * 1728 + ci * 9;
        wino_u(g9, U16);
#pragma unroll
        for (int tp = 0; tp < 16; tp++)
            g_ugru[tp * 16384 + ci * 128 + co] = U16[tp];
        return;
    }
    int k = idx - 24576;
    if (k < 128)
        g_bgru[k] = (k < 64) ? gates_b[64 + k] : can_b[k - 64];
}

// ---------------- output: out[b,h,w,o] = mlp_w[o,:]·h1[b,0,:,w,79-h]+mlp_b ----
__global__ void k_out(const float* __restrict__ mlp_w,
                      const float* __restrict__ mlp_b,
                      float* __restrict__ out) {
    __shared__ float sW[64 * 65];
    __shared__ float sx[4][64];
    int t = threadIdx.x;
    for (int idx = t; idx < 4096; idx += 256) {
        int o = idx >> 6, c = idx & 63;
        sW[c * 65 + o] = mlp_w[idx];
    }
    int pix = t >> 6, o = t & 63;
    int pp = blockIdx.x * 4 + pix;
    int b = pp / NPIX, pr = pp % NPIX;
    int h = pr / HW, w = pr % HW;
    int q = w * HW + (HW - 1 - h);
    sx[pix][o] = g_y[(b * 4) * 64 * NPIX + o * NPIX + q];
    __syncthreads();
    float acc = mlp_b[o];
#pragma unroll 8
    for (int c = 0; c < 64; c++)
        acc = fmaf(sx[pix][c], sW[c * 65 + o], acc);
    out[pp * 64 + o] = acc;
}

// ---------------- host orchestration ----------------
extern "C" void kernel_launch(void* const* d_in, const int* in_sizes, int n_in,
                              void* d_out, int out_size) {
    const float* x       = (const float*)d_in[0];
    const float* pt      = (const float*)d_in[2];
    const float* msg_w   = (const float*)d_in[4];
    const float* msg_b   = (const float*)d_in[5];
    const float* gates_w = (const float*)d_in[6];
    const float* gates_b = (const float*)d_in[7];
    const float* can_w   = (const float*)d_in[8];
    const float* can_b   = (const float*)d_in[9];
    const float* mlp_w   = (const float*)d_in[10];
    const float* mlp_b   = (const float*)d_in[11];

    float *p_y, *p_nbr, *p_convn, *p_ego, *p_agg, *p_gru, *p_mask, *p_bgru;
    float *p_unbr, *p_uego, *p_ugru;
    cudaGetSymbolAddress((void**)&p_y, g_y);
    cudaGetSymbolAddress((void**)&p_nbr, g_nbr);
    cudaGetSymbolAddress((void**)&p_convn, g_convn);
    cudaGetSymbolAddress((void**)&p_ego, g_ego);
    cudaGetSymbolAddress((void**)&p_agg, g_agg);
    cudaGetSymbolAddress((void**)&p_gru, g_gru);
    cudaGetSymbolAddress((void**)&p_mask, g_mask);
    cudaGetSymbolAddress((void**)&p_unbr, g_unbr);
    cudaGetSymbolAddress((void**)&p_uego, g_uego);
    cudaGetSymbolAddress((void**)&p_ugru, g_ugru);
    cudaGetSymbolAddress((void**)&p_bgru, g_bgru);

    const int smemB = SM_FLOATS * 4;     // 69632 B dynamic shared
    cudaFuncSetAttribute(winog_k<64, 64>,
                         cudaFuncAttributeMaxDynamicSharedMemorySize, smemB);
    cudaFuncSetAttribute(winog_k<128, 128>,
                         cudaFuncAttributeMaxDynamicSharedMemorySize, smemB);

    k_minv<<<1, 32>>>(pt);
    k_uprep<<<(24576 + 128 + 255) / 256, 256>>>(msg_w, gates_w, gates_b,
                                                can_w, can_b);
    k_mask<<<dim3(25, NPAIR), 256>>>();
    k_masksum<<<dim3(25, NIMG), 256>>>();
    k_transform<<<(NIMG * 64 * NPIX) / 256, 256>>>(x);

    for (int it = 0; it < 2; it++) {
        k_warp<<<dim3(25, NPAIR), 256>>>();
        // conv(neighbors): 32 imgs, 64->64, no bias, mask-skippable
        winog_k<64, 64><<<dim3(50, 2, NPAIR), 256, smemB>>>(
            p_nbr, 64 * NPIX, p_nbr, 0, 64, p_unbr, nullptr, p_mask,
            p_convn, 64 * NPIX);
        // conv(ego): 8 imgs, 64->64, + msg_b
        winog_k<64, 64><<<dim3(50, 2, NIMG), 256, smemB>>>(
            p_y, 64 * NPIX, p_y, 0, 64, p_uego, msg_b, nullptr,
            p_ego, 64 * NPIX);
        k_agg<<<dim3(25, NIMG), 256>>>();
        // fused GRU conv: [y|agg] 128 -> [update|cand] 128
        winog_k<128, 128><<<dim3(50, 4, NIMG), 256, smemB>>>(
            p_y, 64 * NPIX, p_agg, 64 * NPIX, 64, p_ugru, p_bgru, nullptr,
            p_gru, 128 * NPIX);
        k_pointwise<<<(NIMG * 64 * NPIX) / 256, 256>>>();
    }

    k_out<<<2 * NPIX / 4, 256>>>(mlp_w, mlp_b, (float*)d_out);
}

// round 7
// speedup vs baseline: 1.1199x; 1.1199x over previous
#include <cuda_runtime.h>
#include <math.h>

#define HW    80
#define NPIX  6400          // 80*80
#define NPAIR 32            // B*L*L
#define NIMG  8             // B*L

typedef unsigned long long ull;

// ---------------- scratch (static __device__, no allocations) ----------------
__device__ float g_minv[NPAIR * 6];
__device__ float g_mask[NPAIR * NPIX];
__device__ float g_masksum[NIMG * NPIX];
__device__ float g_y[NIMG * 64 * NPIX];        // ping
__device__ float g_y2[NIMG * 64 * NPIX];       // pong
__device__ float g_convn[NPAIR * 64 * NPIX];   // conv(neighbor)
__device__ float g_ego[NIMG * 64 * NPIX];      // conv(ego)+bias
__device__ float2 g_wnbr2[32 * 64 * 9];        // [co2][cin][tap] cout-paired
__device__ float2 g_wego2[32 * 64 * 9];
__device__ float2 g_wgru2[64 * 128 * 9];       // [(upd,cand) pair][ci][tap]
__device__ float2 g_bgru2[64];                 // (gates_b[64+j], can_b[j])

// ---------------- packed fp32x2 helpers (sm_103a FFMA2) ----------------
__device__ __forceinline__ void fma2(ull& d, ull a, ull b) {
    asm("fma.rn.f32x2 %0, %1, %2, %0;" : "+l"(d) : "l"(a), "l"(b));
}
__device__ __forceinline__ ull bcast2(float v) {
    ull r;
    asm("mov.b64 %0, {%1, %1};" : "=l"(r) : "f"(v));
    return r;
}
__device__ __forceinline__ float2 unpack2(ull v) {
    float2 f;
    asm("mov.b64 {%0, %1}, %2;" : "=f"(f.x), "=f"(f.y) : "l"(v));
    return f;
}

// accurate activations (avoid fast-math tanh.approx)
__device__ __forceinline__ float sigmoid_acc(float u) {
    return 1.0f / (1.0f + expf(-u));
}
__device__ __forceinline__ float tanh_acc(float x) {
    float a = fabsf(x);
    float e = expf(-2.0f * a);
    float t = (1.0f - e) / (1.0f + e);
    return copysignf(t, x);
}

// ---------------- affine inverse: replicate reference fp32 arithmetic -------
__global__ void k_minv(const float* __restrict__ P) {
    int p = threadIdx.x;
    if (p >= NPAIR) return;
    const float* M = P + p * 16;
    float a = M[0], b = M[1];
    float c = M[4], d = M[5];
    float txs = __fdiv_rn(M[3], 0.8f);
    float tys = __fdiv_rn(M[7], 0.8f);
    const float cx = 40.0f, cy = 40.0f;
    float dot0 = __fadd_rn(__fmul_rn(a, cx), __fmul_rn(b, cy));
    float dot1 = __fadd_rn(__fmul_rn(c, cx), __fmul_rn(d, cy));
    float Tx = __fadd_rn(__fsub_rn(cx, dot0), txs);
    float Ty = __fadd_rn(__fsub_rn(cy, dot1), tys);

    float ra  = __fdiv_rn(1.0f, a);
    float l10 = __fmul_rn(c, ra);
    float u22 = __fmaf_rn(-l10, b, d);
    float u23 = __fmaf_rn(-l10, Tx, Ty);

    float x1_0 = __fdiv_rn(-l10, u22);
    float x0_0 = __fdiv_rn(__fmaf_rn(-b, x1_0, 1.0f), a);
    float x1_1 = __fdiv_rn(1.0f, u22);
    float x0_1 = __fdiv_rn(__fmul_rn(-b, x1_1), a);
    float x1_2 = __fdiv_rn(-u23, u22);
    float x0_2 = __fdiv_rn(__fmaf_rn(-b, x1_2, -Tx), a);

    float* o = g_minv + p * 6;
    o[0] = x0_0; o[1] = x0_1; o[2] = x0_2;
    o[3] = x1_0; o[4] = x1_1; o[5] = x1_2;
}

__device__ __forceinline__ float coordx(const float* mv, float x, float y) {
    float s = __fmul_rn(mv[0], x);
    s = __fmaf_rn(mv[1], y, s);
    return __fadd_rn(s, mv[2]);
}
__device__ __forceinline__ float coordy(const float* mv, float x, float y) {
    float s = __fmul_rn(mv[3], x);
    s = __fmaf_rn(mv[4], y, s);
    return __fadd_rn(s, mv[5]);
}

// ---------------- nearest-warp validity mask ----------------
__global__ void k_mask() {
    int pair = blockIdx.y;
    int p = blockIdx.x * 256 + threadIdx.x;
    if (p >= NPIX) return;
    const float* mv = g_minv + pair * 6;
    float x = (float)(p % HW), y = (float)(p / HW);
    float sx = coordx(mv, x, y);
    float sy = coordy(mv, x, y);
    int ix = (int)rintf(sx);
    int iy = (int)rintf(sy);
    g_mask[pair * NPIX + p] =
        (ix >= 0 && ix < HW && iy >= 0 && iy < HW) ? 1.0f : 0.0f;
}

__global__ void k_masksum() {
    int bj = blockIdx.y;
    int p = blockIdx.x * 256 + threadIdx.x;
    if (p >= NPIX) return;
    int b = bj >> 2, j = bj & 3;
    float s = 0.0f;
#pragma unroll
    for (int i = 0; i < 4; i++)
        s += g_mask[((b * 4 + i) * 4 + j) * NPIX + p];
    g_masksum[bj * NPIX + p] = s;
}

// ---------------- initial transform: y[c,h,w] = x[c, 79-w, h] ----------------
__global__ void k_transform(const float* __restrict__ x) {
    int idx = blockIdx.x * 256 + threadIdx.x;
    int p = idx % NPIX;
    int c = (idx / NPIX) & 63;
    int bl = idx / (NPIX * 64);
    int h = p / HW, w = p % HW;
    g_y[idx] = x[(bl * 64 + c) * NPIX + (HW - 1 - w) * HW + h];
}

// ======== fused tiled direct 3x3 conv (SAME), NCHW fp32, FFMA2 ========
// MODE 0 (NBR): input = bilinear warp of ysrc[b,i] (coords precomputed/block),
//               mask-skippable, out = convn[pair]
// MODE 1 (EGO): input = ysrc[img], bias=msg_b, out = ego[img]
// MODE 2 (GRU): input ci<64 = ysrc[img], ci>=64 = masked-mean agg computed
//               on the fly; lanes paired (update,cand); epilogue
//               sigmoid(u)*tanh(c) -> ydst[img]
// Block: 256 thr. Tile 16x16 px. Thread: 4 px x 8 lane-pairs.
template <int MODE, int CIN>
__global__ __launch_bounds__(256, 2)
void conv_fused(const float* __restrict__ ysrc,
                const float* __restrict__ convn,
                const float* __restrict__ ego,
                const float2* __restrict__ Wt2,
                const float* __restrict__ bias,     // MODE1 only (may be null)
                const float2* __restrict__ bgru2,   // MODE2 only
                float* __restrict__ outp) {
    __shared__ float sX[8][18][20];
    __shared__ float2 sW2[32 * 72];
    __shared__ union {
        struct { float4 w[324]; int4 iv[324]; } nbr;
        struct { float mk[324][5]; } gru;
    } aux;

    const int img = blockIdx.z;
    const int tx = blockIdx.x % 5, ty = blockIdx.x / 5;
    const int w0 = tx * 16, h0 = ty * 16;
    const int t = threadIdx.x;
    const int s = t & 63;
    const int wl = s & 15;
    const int hq = s >> 4;
    const int cg = t >> 6;

    const float* srcI = nullptr;     // direct-conv input image base
    if (MODE == 0) {
        // mask-skip: conv output is multiplied by mask later
        const float* mp = g_mask + (long)img * NPIX;
        int any = 0;
#pragma unroll
        for (int k = 0; k < 4; k++)
            any |= (mp[(h0 + hq * 4 + k) * HW + (w0 + wl)] != 0.0f);
        if (__syncthreads_count(any) == 0) return;
        // per-block bilinear coords for the 18x18 halo
        int b = img >> 4, i = (img >> 2) & 3;
        srcI = ysrc + (long)(b * 4 + i) * 64 * NPIX;
        const float* mv = g_minv + img * 6;
        for (int idx = t; idx < 324; idx += 256) {
            int r = idx / 18, c = idx % 18;
            int gh = h0 - 1 + r, gw = w0 - 1 + c;
            float4 wv = make_float4(0.f, 0.f, 0.f, 0.f);
            int4 iv = make_int4(0, 0, 0, 0);
            if (gh >= 0 && gh < HW && gw >= 0 && gw < HW) {
                float x = (float)gw, y = (float)gh;
                float sx = coordx(mv, x, y);
                float sy = coordy(mv, x, y);
                float x0f = floorf(sx), y0f = floorf(sy);
                float fx = __fsub_rn(sx, x0f), fy = __fsub_rn(sy, y0f);
                int x0 = (int)x0f, y0 = (int)y0f;
                int x1 = x0 + 1, y1 = y0 + 1;
                int cx0 = min(max(x0, 0), HW - 1), cx1 = min(max(x1, 0), HW - 1);
                int cy0 = min(max(y0, 0), HW - 1), cy1 = min(max(y1, 0), HW - 1);
                float vx0 = (x0 >= 0 && x0 < HW) ? 1.0f : 0.0f;
                float vx1 = (x1 >= 0 && x1 < HW) ? 1.0f : 0.0f;
                float vy0 = (y0 >= 0 && y0 < HW) ? 1.0f : 0.0f;
                float vy1 = (y1 >= 0 && y1 < HW) ? 1.0f : 0.0f;
                float gx = __fsub_rn(1.0f, fx), gy = __fsub_rn(1.0f, fy);
                wv.x = __fmul_rn(__fmul_rn(vx0, vy0), __fmul_rn(gx, gy));
                wv.y = __fmul_rn(__fmul_rn(vx1, vy0), __fmul_rn(fx, gy));
                wv.z = __fmul_rn(__fmul_rn(vx0, vy1), __fmul_rn(gx, fy));
                wv.w = __fmul_rn(__fmul_rn(vx1, vy1), __fmul_rn(fx, fy));
                iv.x = cy0 * HW + cx0; iv.y = cy0 * HW + cx1;
                iv.z = cy1 * HW + cx0; iv.w = cy1 * HW + cx1;
            }
            aux.nbr.w[idx] = wv;
            aux.nbr.iv[idx] = iv;
        }
        __syncthreads();
    } else if (MODE == 1) {
        srcI = ysrc + (long)img * 64 * NPIX;
    } else {
        srcI = ysrc + (long)img * 64 * NPIX;
        // preload masks for agg (ms, m0..m3) on the halo
        int b = img >> 2, j = img & 3;
        for (int idx = t; idx < 324; idx += 256) {
            int r = idx / 18, c = idx % 18;
            int gh = h0 - 1 + r, gw = w0 - 1 + c;
            float ms = 0.f, m0 = 0.f, m1 = 0.f, m2 = 0.f, m3 = 0.f;
            if (gh >= 0 && gh < HW && gw >= 0 && gw < HW) {
                int p = gh * HW + gw;
                ms = g_masksum[img * NPIX + p];
                m0 = g_mask[((b * 4 + 0) * 4 + j) * NPIX + p];
                m1 = g_mask[((b * 4 + 1) * 4 + j) * NPIX + p];
                m2 = g_mask[((b * 4 + 2) * 4 + j) * NPIX + p];
                m3 = g_mask[((b * 4 + 3) * 4 + j) * NPIX + p];
            }
            aux.gru.mk[idx][0] = ms; aux.gru.mk[idx][1] = m0;
            aux.gru.mk[idx][2] = m1; aux.gru.mk[idx][3] = m2;
            aux.gru.mk[idx][4] = m3;
        }
        __syncthreads();
    }

    ull acc2[4][8];
#pragma unroll
    for (int k = 0; k < 4; k++)
#pragma unroll
        for (int j = 0; j < 8; j++) acc2[k][j] = 0ULL;

    for (int cin0 = 0; cin0 < CIN; cin0 += 8) {
        // ---- stage input tile with halo: 8ci x 18 x 18 ----
        for (int idx = t; idx < 8 * 324; idx += 256) {
            int ci = idx / 324, rem = idx % 324;
            int r = rem / 18, c = rem % 18;
            float v = 0.0f;
            if (MODE == 0) {
                float4 wv = aux.nbr.w[rem];
                int4 iv = aux.nbr.iv[rem];
                const float* sc = srcI + (cin0 + ci) * NPIX;
                v = __fmul_rn(wv.x, sc[iv.x]);
                v = __fadd_rn(v, __fmul_rn(wv.y, sc[iv.y]));
                v = __fadd_rn(v, __fmul_rn(wv.z, sc[iv.z]));
                v = __fadd_rn(v, __fmul_rn(wv.w, sc[iv.w]));
            } else {
                int gh = h0 - 1 + r, gw = w0 - 1 + c;
                if (gh >= 0 && gh < HW && gw >= 0 && gw < HW) {
                    int p = gh * HW + gw;
                    if (MODE == 1 || cin0 < 64) {
                        v = srcI[(cin0 + ci) * NPIX + p];
                    } else {
                        int cb = cin0 - 64 + ci;
                        int b = img >> 2, j = img & 3;
                        float ms = aux.gru.mk[rem][0];
                        v = __fmul_rn(ms, ego[((long)img * 64 + cb) * NPIX + p]);
                        v = __fmaf_rn(aux.gru.mk[rem][1],
                                      convn[((long)((b * 4 + 0) * 4 + j) * 64 + cb) * NPIX + p], v);
                        v = __fmaf_rn(aux.gru.mk[rem][2],
                                      convn[((long)((b * 4 + 1) * 4 + j) * 64 + cb) * NPIX + p], v);
                        v = __fmaf_rn(aux.gru.mk[rem][3],
                                      convn[((long)((b * 4 + 2) * 4 + j) * 64 + cb) * NPIX + p], v);
                        v = __fmaf_rn(aux.gru.mk[rem][4],
                                      convn[((long)((b * 4 + 3) * 4 + j) * 64 + cb) * NPIX + p], v);
                        v = __fmul_rn(0.25f, v);
                    }
                }
            }
            sX[ci][r][c] = v;
        }
        // ---- stage weights: 32 pairs x 8ci x 9 (float2) ----
        for (int idx = t; idx < 32 * 72; idx += 256) {
            int co2 = idx / 72, rem = idx % 72;
            sW2[co2 * 72 + rem] =
                Wt2[((blockIdx.y * 32 + co2) * CIN + cin0) * 9 + rem];
        }
        __syncthreads();
#pragma unroll 1
        for (int ci = 0; ci < 8; ci++) {
            ull xb[6][3];
#pragma unroll
            for (int rr = 0; rr < 6; rr++)
#pragma unroll
                for (int cc = 0; cc < 3; cc++)
                    xb[rr][cc] = bcast2(sX[ci][hq * 4 + rr][wl + cc]);
            const float2* wp = &sW2[(cg * 8) * 72 + ci * 9];
#pragma unroll
            for (int j = 0; j < 8; j++) {
#pragma unroll
                for (int tap = 0; tap < 9; tap++) {
                    ull w2 = *reinterpret_cast<const ull*>(&wp[j * 72 + tap]);
                    int r = tap / 3, c = tap % 3;
                    fma2(acc2[0][j], xb[0 + r][c], w2);
                    fma2(acc2[1][j], xb[1 + r][c], w2);
                    fma2(acc2[2][j], xb[2 + r][c], w2);
                    fma2(acc2[3][j], xb[3 + r][c], w2);
                }
            }
        }
        __syncthreads();
    }
    // ---- epilogue ----
    if (MODE == 2) {
#pragma unroll
        for (int j = 0; j < 8; j++) {
            int pr = blockIdx.y * 32 + cg * 8 + j;   // y channel
            float2 bb = bgru2[pr];
#pragma unroll
            for (int k = 0; k < 4; k++) {
                int h = h0 + hq * 4 + k, w = w0 + wl;
                float2 f = unpack2(acc2[k][j]);
                float u = f.x + bb.x;
                float cd = f.y + bb.y;
                outp[((long)img * 64 + pr) * NPIX + h * HW + w] =
                    sigmoid_acc(u) * tanh_acc(cd);
            }
        }
    } else {
#pragma unroll
        for (int j = 0; j < 8; j++) {
            int co = blockIdx.y * 64 + cg * 16 + 2 * j;
            float bv0 = (MODE == 1 && bias) ? bias[co] : 0.0f;
            float bv1 = (MODE == 1 && bias) ? bias[co + 1] : 0.0f;
#pragma unroll
            for (int k = 0; k < 4; k++) {
                int h = h0 + hq * 4 + k, w = w0 + wl;
                float2 f = unpack2(acc2[k][j]);
                outp[((long)img * 64 + co) * NPIX + h * HW + w] = f.x + bv0;
                outp[((long)img * 64 + co + 1) * NPIX + h * HW + w] = f.y + bv1;
            }
        }
    }
}

// ---------------- weight prepack ----------------
__global__ void k_prepack(const float* __restrict__ msg_w,
                          const float* __restrict__ gates_w,
                          const float* __restrict__ gates_b,
                          const float* __restrict__ can_w,
                          const float* __restrict__ can_b) {
    int idx = blockIdx.x * 256 + threadIdx.x;
    if (idx < 18432) {                         // msg split: [co2][ci<64][9]
        int co2 = idx / 576, rem = idx % 576;
        int coA = 2 * co2, coB = 2 * co2 + 1;
        g_wnbr2[idx] = make_float2(msg_w[coA * 1152 + rem],
                                   msg_w[coB * 1152 + rem]);
        g_wego2[idx] = make_float2(msg_w[coA * 1152 + 576 + rem],
                                   msg_w[coB * 1152 + 576 + rem]);
        return;
    }
    int k = idx - 18432;
    if (k < 73728) {                           // gru (update,cand) lane pairs
        int pr = k / 1152, rem = k % 1152;     // rem = ci*9+tap, ci<128
        g_wgru2[k] = make_float2(gates_w[(64 + pr) * 1728 + rem],
                                 can_w[pr * 1728 + rem]);
        return;
    }
    k -= 73728;
    if (k < 64)
        g_bgru2[k] = make_float2(gates_b[64 + k], can_b[k]);
}

// ---------------- output: out[b,h,w,o] = mlp_w[o,:]·h1[b,0,:,w,79-h]+mlp_b ----
__global__ void k_out(const float* __restrict__ mlp_w,
                      const float* __restrict__ mlp_b,
                      float* __restrict__ out) {
    __shared__ float sW[64 * 65];
    __shared__ float sx[4][64];
    int t = threadIdx.x;
    for (int idx = t; idx < 4096; idx += 256) {
        int o = idx >> 6, c = idx & 63;
        sW[c * 65 + o] = mlp_w[idx];
    }
    int pix = t >> 6, o = t & 63;
    int pp = blockIdx.x * 4 + pix;
    int b = pp / NPIX, pr = pp % NPIX;
    int h = pr / HW, w = pr % HW;
    int q = w * HW + (HW - 1 - h);
    sx[pix][o] = g_y[(b * 4) * 64 * NPIX + o * NPIX + q];
    __syncthreads();
    float acc = mlp_b[o];
#pragma unroll 8
    for (int c = 0; c < 64; c++)
        acc = fmaf(sx[pix][c], sW[c * 65 + o], acc);
    out[pp * 64 + o] = acc;
}

// ---------------- host orchestration ----------------
extern "C" void kernel_launch(void* const* d_in, const int* in_sizes, int n_in,
                              void* d_out, int out_size) {
    const float* x       = (const float*)d_in[0];
    const float* pt      = (const float*)d_in[2];
    const float* msg_w   = (const float*)d_in[4];
    const float* msg_b   = (const float*)d_in[5];
    const float* gates_w = (const float*)d_in[6];
    const float* gates_b = (const float*)d_in[7];
    const float* can_w   = (const float*)d_in[8];
    const float* can_b   = (const float*)d_in[9];
    const float* mlp_w   = (const float*)d_in[10];
    const float* mlp_b   = (const float*)d_in[11];

    float *p_y, *p_y2, *p_convn, *p_ego;
    float2 *p_wnbr2, *p_wego2, *p_wgru2, *p_bgru2;
    cudaGetSymbolAddress((void**)&p_y, g_y);
    cudaGetSymbolAddress((void**)&p_y2, g_y2);
    cudaGetSymbolAddress((void**)&p_convn, g_convn);
    cudaGetSymbolAddress((void**)&p_ego, g_ego);
    cudaGetSymbolAddress((void**)&p_wnbr2, g_wnbr2);
    cudaGetSymbolAddress((void**)&p_wego2, g_wego2);
    cudaGetSymbolAddress((void**)&p_wgru2, g_wgru2);
    cudaGetSymbolAddress((void**)&p_bgru2, g_bgru2);

    k_minv<<<1, 32>>>(pt);
    k_prepack<<<(18432 + 73728 + 64 + 255) / 256, 256>>>(msg_w, gates_w,
                                                         gates_b, can_w, can_b);
    k_mask<<<dim3(25, NPAIR), 256>>>();
    k_masksum<<<dim3(25, NIMG), 256>>>();
    k_transform<<<(NIMG * 64 * NPIX) / 256, 256>>>(x);

    for (int it = 0; it < 2; it++) {
        const float* ysrc = (it == 0) ? p_y : p_y2;
        float* ydst       = (it == 0) ? p_y2 : p_y;
        // neighbor conv with fused bilinear warp: 32 pairs, 64->64
        conv_fused<0, 64><<<dim3(25, 1, NPAIR), 256>>>(
            ysrc, nullptr, nullptr, p_wnbr2, nullptr, nullptr, p_convn);
        // ego conv: 8 imgs, 64->64, + msg_b
        conv_fused<1, 64><<<dim3(25, 1, NIMG), 256>>>(
            ysrc, nullptr, nullptr, p_wego2, msg_b, nullptr, p_ego);
        // GRU conv with fused agg + pointwise: 8 imgs, 128->64 (u,c pairs)
        conv_fused<2, 128><<<dim3(25, 2, NIMG), 256>>>(
            ysrc, p_convn, p_ego, p_wgru2, nullptr, p_bgru2, ydst);
    }

    k_out<<<2 * NPIX / 4, 256>>>(mlp_w, mlp_b, (float*)d_out);
}